// round 7
// baseline (speedup 1.0000x reference)
#include <cuda_runtime.h>
#include <cstdint>
#include <cstddef>

#define NN 50000
#define NE 800000
#define NG 128
#define D  128
#define NL 4
#define NC 10
#define GN_EPS 1e-5f
#define SLOTW 128
#define NT 391                    // ceil(NN/128) M-tiles

// packed-fragment layouts (float4 units)
#define PA4 68                    // A smem pitch (float4) : 128 rows x 64 pairs (+4 pad)
#define PW4 20                    // W smem pitch (float4) : 128 n x 16 pairs (+4 pad)
#define OFF_W (128 * PA4)
#define FMLP_SMEM_BYTES ((128 * PA4 + 128 * PW4) * 16)

// ---------------- scratch ----------------
__device__ float  g_H[NN * D];
__device__ float  g_B[NN * D];
__device__ float4 g_Apk[(size_t)NT * 128 * 64];   // packed A (hiL,hiR,loL,loR)
__device__ float4 g_Wpk[4 * 2 * 128 * 64];        // packed W per layer/mat
__device__ float  g_pool[NG * D];
__device__ float  g_f1[NG * D];
__device__ float  g_f2[NG * D];
__device__ int    g_off[NG + 1];
__device__ int    g_is64;
__device__ int    g_deg[NN];
__device__ int    g_slots[(size_t)NN * SLOTW];

// ---------------- helpers ----------------
__device__ __forceinline__ uint32_t f2tf32(float x) {
    uint32_t r;
    asm("cvt.rna.tf32.f32 %0, %1;" : "=r"(r) : "f"(x));
    return r;
}
__device__ __forceinline__ float4 packsplit(float L, float R) {
    uint32_t hL = f2tf32(L), hR = f2tf32(R);
    float4 o;
    o.x = __uint_as_float(hL);
    o.y = __uint_as_float(hR);
    o.z = __uint_as_float(f2tf32(L - o.x));
    o.w = __uint_as_float(f2tf32(R - o.y));
    return o;
}
__device__ __forceinline__ void mma8(float* d, const uint32_t* a, uint32_t b0, uint32_t b1) {
    asm volatile(
        "mma.sync.aligned.m16n8k8.row.col.f32.tf32.tf32.f32 "
        "{%0,%1,%2,%3}, {%4,%5,%6,%7}, {%8,%9}, {%0,%1,%2,%3};"
        : "+f"(d[0]), "+f"(d[1]), "+f"(d[2]), "+f"(d[3])
        : "r"(a[0]), "r"(a[1]), "r"(a[2]), "r"(a[3]), "r"(b0), "r"(b1));
}

// ---------------- prep kernels ----------------
__global__ void detect_kernel(const int* __restrict__ p) {
    if (threadIdx.x == 0 && blockIdx.x == 0) {
        int s = 0;
        for (int i = 0; i < 128; i++) s |= p[2 * i + 1];
        g_is64 = (s == 0) ? 1 : 0;
    }
}

__global__ void zerodeg_kernel() {
    int i = blockIdx.x * blockDim.x + threadIdx.x;
    if (i < NN) g_deg[i] = 0;
}

__global__ void offsets_kernel(const void* __restrict__ batch_raw, int n) {
    int i = blockIdx.x * blockDim.x + threadIdx.x;
    if (i >= n) return;
    const int is64 = g_is64;
    const int* b32 = (const int*)batch_raw;
    const long long* b64 = (const long long*)batch_raw;
    int b = is64 ? (int)b64[i] : b32[i];
    if (i == 0) {
        for (int g = 0; g <= b; g++) g_off[g] = 0;
    } else {
        int p = is64 ? (int)b64[i - 1] : b32[i - 1];
        if (b != p) for (int g = p + 1; g <= b; g++) g_off[g] = i;
    }
    if (i == n - 1) {
        for (int g = b + 1; g <= NG; g++) g_off[g] = n;
    }
}

__global__ void fill_kernel(const void* __restrict__ ei_raw) {
    int i = blockIdx.x * blockDim.x + threadIdx.x;
    if (i >= NE) return;
    int s, d;
    if (g_is64) {
        const long long* e = (const long long*)ei_raw;
        s = (int)e[i];
        d = (int)e[NE + i];
    } else {
        const int* e = (const int*)ei_raw;
        s = e[i];
        d = e[NE + i];
    }
    int pos = atomicAdd(&g_deg[d], 1);
    if (pos < SLOTW) g_slots[(size_t)d * SLOTW + pos] = s;
}

// W pack: Wpk[l][m][n][p] = (hi W[k][n], hi W[k+4][n], lo W[k][n], lo W[k+4][n]),
// p = ks*4+r, k = ks*8+r
__global__ void wsplit_kernel(const float* __restrict__ gw1, const float* __restrict__ gw2) {
    int idx = blockIdx.x * blockDim.x + threadIdx.x;   // 4*2*128*64 = 65536
    if (idx >= 4 * 2 * 128 * 64) return;
    int p = idx & 63;
    int n = (idx >> 6) & 127;
    int m = (idx >> 13) & 1;
    int l = idx >> 14;
    int k = (p >> 2) * 8 + (p & 3);
    const float* src = (m ? gw2 : gw1) + (size_t)l * 16384;
    g_Wpk[idx] = packsplit(src[k * 128 + n], src[(k + 4) * 128 + n]);
}

// ---------------- gather aggregation -> packed fragment tiles ----------------
__global__ void __launch_bounds__(256) agg_kernel(const float* __restrict__ in) {
    int n = (blockIdx.x * blockDim.x + threadIdx.x) >> 5;
    int lane = threadIdx.x & 31;
    if (n >= NN) return;
    const float4* in4 = (const float4*)in;
    const int* sl = g_slots + (size_t)n * SLOTW;
    int deg = g_deg[n];
    if (deg > SLOTW) deg = SLOTW;

    float4 acc = in4[(size_t)n * 32 + lane];   // cols 4*lane .. 4*lane+3
    int e = 0;
    for (; e + 4 <= deg; e += 4) {
        int s0 = sl[e], s1 = sl[e + 1], s2 = sl[e + 2], s3 = sl[e + 3];
        float4 v0 = in4[(size_t)s0 * 32 + lane];
        float4 v1 = in4[(size_t)s1 * 32 + lane];
        float4 v2 = in4[(size_t)s2 * 32 + lane];
        float4 v3 = in4[(size_t)s3 * 32 + lane];
        acc.x += v0.x + v1.x + v2.x + v3.x;
        acc.y += v0.y + v1.y + v2.y + v3.y;
        acc.z += v0.z + v1.z + v2.z + v3.z;
        acc.w += v0.w + v1.w + v2.w + v3.w;
    }
    for (; e < deg; e++) {
        int s0 = sl[e];
        float4 v0 = in4[(size_t)s0 * 32 + lane];
        acc.x += v0.x; acc.y += v0.y; acc.z += v0.z; acc.w += v0.w;
    }
    // repack: lane 2a holds cols 8a..8a+3 (L halves), lane 2a+1 cols 8a+4..8a+7 (R halves)
    float px = __shfl_xor_sync(0xFFFFFFFFu, acc.x, 1);
    float py = __shfl_xor_sync(0xFFFFFFFFu, acc.y, 1);
    float pz = __shfl_xor_sync(0xFFFFFFFFu, acc.z, 1);
    float pw = __shfl_xor_sync(0xFFFFFFFFu, acc.w, 1);
    int a = lane >> 1;
    float4* dst = g_Apk + (size_t)n * 64;
    if ((lane & 1) == 0) {
        dst[a * 4 + 0] = packsplit(acc.x, px);   // pr0: cols (8a, 8a+4)
        dst[a * 4 + 1] = packsplit(acc.y, py);   // pr1
    } else {
        dst[a * 4 + 2] = packsplit(pz, acc.z);   // pr2: cols (8a+2, 8a+6)
        dst[a * 4 + 3] = packsplit(pw, acc.w);   // pr3
    }
}

// ---------------- fused MLP on tensor cores, packed fragments ----------------
__global__ void __launch_bounds__(256, 1) mma_mlp_kernel(
    const float4* __restrict__ Apk, const float4* __restrict__ Wpk,
    const float* __restrict__ b1, const float* __restrict__ b2,
    float* __restrict__ C, int M)
{
    extern __shared__ float4 sm4[];
    float4* As = sm4;             // [128][PA4]
    float4* Ws = sm4 + OFF_W;     // [128][PW4]

    int tid = threadIdx.x;
    int w = tid >> 5;
    int lane = tid & 31;
    int wm = w & 3;
    int wn = w >> 2;
    int q = lane >> 2;
    int r = lane & 3;
    int m0 = blockIdx.x * 128;

    // load packed A tile
#pragma unroll
    for (int t = 0; t < 32; t++) {
        int i = t * 256 + tid;
        As[(i >> 6) * PA4 + (i & 63)] = Apk[(size_t)(m0 + (i >> 6)) * 64 + (i & 63)];
    }

    float dacc[2][8][4];

    for (int ph = 0; ph < 2; ph++) {
        const float4* Wsrc = Wpk + (size_t)ph * 128 * 64;
#pragma unroll
        for (int mt = 0; mt < 2; mt++)
#pragma unroll
            for (int nt = 0; nt < 8; nt++)
#pragma unroll
                for (int j = 0; j < 4; j++) dacc[mt][nt][j] = 0.f;

        for (int chunk = 0; chunk < 4; chunk++) {
            __syncthreads();
#pragma unroll
            for (int t = 0; t < 8; t++) {
                int i = t * 256 + tid;
                int nn = i >> 4, j = i & 15;
                Ws[nn * PW4 + j] = Wsrc[nn * 64 + chunk * 16 + j];
            }
            __syncthreads();

#pragma unroll
            for (int ksc = 0; ksc < 4; ksc++) {
                int pA = (chunk * 4 + ksc) * 4 + r;
                uint32_t ah[2][4], al[2][4];
#pragma unroll
                for (int mt = 0; mt < 2; mt++) {
                    int rb = wm * 32 + mt * 16 + q;
                    float4 v0 = As[rb * PA4 + pA];
                    float4 v1 = As[(rb + 8) * PA4 + pA];
                    ah[mt][0] = __float_as_uint(v0.x);
                    ah[mt][1] = __float_as_uint(v1.x);
                    ah[mt][2] = __float_as_uint(v0.y);
                    ah[mt][3] = __float_as_uint(v1.y);
                    al[mt][0] = __float_as_uint(v0.z);
                    al[mt][1] = __float_as_uint(v1.z);
                    al[mt][2] = __float_as_uint(v0.w);
                    al[mt][3] = __float_as_uint(v1.w);
                }
#pragma unroll
                for (int nt = 0; nt < 8; nt++) {
                    int nb = wn * 64 + nt * 8 + q;
                    float4 wv = Ws[nb * PW4 + ksc * 4 + r];
                    uint32_t bh0 = __float_as_uint(wv.x);
                    uint32_t bh1 = __float_as_uint(wv.y);
                    uint32_t bl0 = __float_as_uint(wv.z);
                    uint32_t bl1 = __float_as_uint(wv.w);
#pragma unroll
                    for (int mt = 0; mt < 2; mt++) {
                        mma8(dacc[mt][nt], ah[mt], bh0, bh1);
                        mma8(dacc[mt][nt], al[mt], bh0, bh1);
                        mma8(dacc[mt][nt], ah[mt], bl0, bl1);
                    }
                }
            }
        }
        __syncthreads();

        if (ph == 0) {
            // epilogue 1: relu(d + b1), shfl-repack into As
#pragma unroll
            for (int mt = 0; mt < 2; mt++) {
                int rw0 = wm * 32 + mt * 16 + q;
#pragma unroll
                for (int nt = 0; nt < 8; nt++) {
                    int c0 = wn * 64 + nt * 8 + 2 * r;
                    float bb0 = __ldg(b1 + c0);
                    float bb1 = __ldg(b1 + c0 + 1);
                    float z0 = fmaxf(dacc[mt][nt][0] + bb0, 0.f);  // (rw0,   c0)
                    float z1 = fmaxf(dacc[mt][nt][1] + bb1, 0.f);  // (rw0,   c0+1)
                    float z2 = fmaxf(dacc[mt][nt][2] + bb0, 0.f);  // (rw0+8, c0)
                    float z3 = fmaxf(dacc[mt][nt][3] + bb1, 0.f);  // (rw0+8, c0+1)
                    float p0 = __shfl_xor_sync(0xFFFFFFFFu, z0, 2);
                    float p1 = __shfl_xor_sync(0xFFFFFFFFu, z1, 2);
                    float p2 = __shfl_xor_sync(0xFFFFFFFFu, z2, 2);
                    float p3 = __shfl_xor_sync(0xFFFFFFFFu, z3, 2);
                    int pb = (wn * 8 + nt) * 4;
                    if (r < 2) {
                        // row rw0, prs 2r / 2r+1: L = own, R = partner
                        As[rw0 * PA4 + pb + 2 * r]     = packsplit(z0, p0);
                        As[rw0 * PA4 + pb + 2 * r + 1] = packsplit(z1, p1);
                    } else {
                        // row rw0+8, prs 2(r-2) / +1: L = partner, R = own
                        As[(rw0 + 8) * PA4 + pb + 2 * (r - 2)]     = packsplit(p2, z2);
                        As[(rw0 + 8) * PA4 + pb + 2 * (r - 2) + 1] = packsplit(p3, z3);
                    }
                }
            }
        } else {
            // epilogue 2: C = relu(d + b2)
#pragma unroll
            for (int mt = 0; mt < 2; mt++) {
                int rw0 = m0 + wm * 32 + mt * 16 + q;
#pragma unroll
                for (int nt = 0; nt < 8; nt++) {
                    int c0 = wn * 64 + nt * 8 + 2 * r;
                    float bb0 = __ldg(b2 + c0);
                    float bb1 = __ldg(b2 + c0 + 1);
                    if (rw0 < M) {
                        float2 o;
                        o.x = fmaxf(dacc[mt][nt][0] + bb0, 0.f);
                        o.y = fmaxf(dacc[mt][nt][1] + bb1, 0.f);
                        *(float2*)(C + (size_t)rw0 * 128 + c0) = o;
                    }
                    if (rw0 + 8 < M) {
                        float2 o;
                        o.x = fmaxf(dacc[mt][nt][2] + bb0, 0.f);
                        o.y = fmaxf(dacc[mt][nt][3] + bb1, 0.f);
                        *(float2*)(C + (size_t)(rw0 + 8) * 128 + c0) = o;
                    }
                }
            }
        }
    }
}

// ---------------- GraphNorm + ReLU, 2-pass ----------------
__global__ void __launch_bounds__(512) graphnorm_kernel(
    const float* __restrict__ in, float* __restrict__ outp,
    const float* __restrict__ w, const float* __restrict__ bi,
    const float* __restrict__ ms, int last)
{
    __shared__ float rs[4][128];
    __shared__ float rq[4][128];
    int g = blockIdx.x;
    int d = threadIdx.x & 127;
    int ty = threadIdx.x >> 7;
    int n0 = g_off[g];
    int n1 = g_off[g + 1];
    float cnt = (float)((n1 - n0) > 0 ? (n1 - n0) : 1);

    float s = 0.f, qq = 0.f;
    for (int i = n0 + ty; i < n1; i += 4) {
        float v = __ldg(in + (size_t)i * D + d);
        s += v;
        qq += v * v;
    }
    rs[ty][d] = s;
    rq[ty][d] = qq;
    __syncthreads();
    float S = rs[0][d] + rs[1][d] + rs[2][d] + rs[3][d];
    float Q = rq[0][d] + rq[1][d] + rq[2][d] + rq[3][d];
    float mu = S / cnt;
    float a = mu * ms[d];
    float var = Q / cnt - 2.f * a * mu + a * a;
    float inv = rsqrtf(var + GN_EPS);
    float wd = w[d], bd = bi[d];

    float ps = 0.f;
    for (int i = n0 + ty; i < n1; i += 4) {
        size_t idx = (size_t)i * D + d;
        float t = __ldg(in + idx) - a;
        float o = fmaxf(wd * t * inv + bd, 0.f);
        outp[idx] = o;
        ps += o;
    }
    if (last) {
        __syncthreads();
        rs[ty][d] = ps;
        __syncthreads();
        if (ty == 0) g_pool[g * D + d] = rs[0][d] + rs[1][d] + rs[2][d] + rs[3][d];
    }
}

// ---------------- small FC ----------------
__global__ void __launch_bounds__(128) fc_kernel(
    const float* __restrict__ in, const float* __restrict__ W,
    const float* __restrict__ bias, float* __restrict__ out, int do_relu)
{
    __shared__ float s[128];
    int g = blockIdx.x;
    int j = threadIdx.x;
    s[j] = in[g * 128 + j];
    __syncthreads();
    float acc = bias[j];
#pragma unroll 8
    for (int k = 0; k < 128; k++) acc += s[k] * W[k * 128 + j];
    out[g * 128 + j] = do_relu ? fmaxf(acc, 0.f) : acc;
}

// ---------------- logits + log_softmax ----------------
__global__ void __launch_bounds__(32) logits_kernel(
    const float* __restrict__ fw3, const float* __restrict__ fb3,
    float* __restrict__ out)
{
    __shared__ float s[128];
    __shared__ float lg[NC];
    __shared__ float lse;
    int g = blockIdx.x;
    int t = threadIdx.x;
    for (int k = t; k < 128; k += 32) s[k] = g_f2[g * 128 + k];
    __syncthreads();
    if (t < NC) {
        float acc = fb3[t];
#pragma unroll 8
        for (int k = 0; k < 128; k++) acc += s[k] * fw3[k * NC + t];
        lg[t] = acc;
    }
    __syncthreads();
    if (t == 0) {
        float mx = lg[0];
        for (int c = 1; c < NC; c++) mx = fmaxf(mx, lg[c]);
        float se = 0.f;
        for (int c = 0; c < NC; c++) se += expf(lg[c] - mx);
        lse = mx + logf(se);
    }
    __syncthreads();
    if (t < NC) out[g * NC + t] = lg[t] - lse;
}

// ---------------- launch ----------------
extern "C" void kernel_launch(void* const* d_in, const int* in_sizes, int n_in,
                              void* d_out, int out_size)
{
    const float* x       = (const float*)d_in[0];
    const float* gw1     = (const float*)d_in[1];
    const float* gb1     = (const float*)d_in[2];
    const float* gw2     = (const float*)d_in[3];
    const float* gb2     = (const float*)d_in[4];
    const float* gnw     = (const float*)d_in[5];
    const float* gnb     = (const float*)d_in[6];
    const float* gns     = (const float*)d_in[7];
    const float* fw1     = (const float*)d_in[8];
    const float* fb1     = (const float*)d_in[9];
    const float* fw2     = (const float*)d_in[10];
    const float* fb2     = (const float*)d_in[11];
    const float* fw3     = (const float*)d_in[12];
    const float* fb3     = (const float*)d_in[13];
    const void*  ei      = d_in[14];
    const void*  batch   = d_in[15];
    float* out = (float*)d_out;

    float *Hp, *Bp, *poolp, *f1p, *f2p;
    float4 *Apkp, *Wpkp;
    cudaGetSymbolAddress((void**)&Hp, g_H);
    cudaGetSymbolAddress((void**)&Bp, g_B);
    cudaGetSymbolAddress((void**)&Apkp, g_Apk);
    cudaGetSymbolAddress((void**)&Wpkp, g_Wpk);
    cudaGetSymbolAddress((void**)&poolp, g_pool);
    cudaGetSymbolAddress((void**)&f1p, g_f1);
    cudaGetSymbolAddress((void**)&f2p, g_f2);

    cudaFuncSetAttribute(mma_mlp_kernel,
                         cudaFuncAttributeMaxDynamicSharedMemorySize,
                         FMLP_SMEM_BYTES);

    detect_kernel<<<1, 32>>>((const int*)ei);
    zerodeg_kernel<<<(NN + 255) / 256, 256>>>();
    offsets_kernel<<<(NN + 255) / 256, 256>>>(batch, NN);
    fill_kernel<<<(NE + 255) / 256, 256>>>(ei);
    wsplit_kernel<<<(4 * 2 * 128 * 64 + 255) / 256, 256>>>(gw1, gw2);

    const int agg_blocks = (NN * 32 + 255) / 256;

    for (int l = 0; l < NL; l++) {
        const float* hin = (l == 0) ? x : Hp;
        agg_kernel<<<agg_blocks, 256>>>(hin);
        mma_mlp_kernel<<<NT, 256, FMLP_SMEM_BYTES>>>(
            Apkp, Wpkp + (size_t)l * 2 * 128 * 64,
            gb1 + l * D, gb2 + l * D, Bp, NN);
        graphnorm_kernel<<<NG, 512>>>(Bp, Hp,
            gnw + l * D, gnb + l * D, gns + l * D, (l == NL - 1) ? 1 : 0);
    }

    fc_kernel<<<NG, 128>>>(poolp, fw1, fb1, f1p, 1);
    fc_kernel<<<NG, 128>>>(f1p, fw2, fb2, f2p, 1);
    logits_kernel<<<NG, 32>>>(fw3, fb3, out);
}